// round 16
// baseline (speedup 1.0000x reference)
#include <cuda_runtime.h>
#include <cuda_bf16.h>
#include <math.h>
#include <stdint.h>

#define FULLMASK 0xffffffffu
#define BATCH 2
#define NHEAD 16
#define KVLEN 4096
#define QLEN  2048
#define HDIM  64
#define HID   1024
#define TOPK  32
#define BH    (BATCH * NHEAD)
#define TK    10
#define MQ    (BATCH * QLEN)
#define MKV   (BATCH * KVLEN)

typedef __nv_bfloat16 bf16;
typedef __nv_bfloat162 bf162;

// ---------------------------------------------------------------------------
// Scratch
// ---------------------------------------------------------------------------
__device__ float g_q[(size_t)BH * QLEN * HDIM];
__device__ float g_k[(size_t)BH * KVLEN * HDIM];
__device__ float g_v[(size_t)BH * KVLEN * HDIM];
__device__ bf16  g_qb[(size_t)BH * QLEN * HDIM];
__device__ bf16  g_kb[(size_t)BH * KVLEN * HDIM];
__device__ bf16  g_scb[(size_t)BH * QLEN * KVLEN];
__device__ bf16  g_vs0[(size_t)MKV * HID], g_vs1[(size_t)MKV * HID];
__device__ bf16  g_wv0[(size_t)HID * HID], g_wv1[(size_t)HID * HID];
__device__ bf16  g_wo0[(size_t)HID * HID], g_wo1[(size_t)HID * HID];
__device__ bf16  g_at0[(size_t)MQ * HID],  g_at1[(size_t)MQ * HID];

// ---------------------------------------------------------------------------
// PTX helpers (sm_80 baseline)
// ---------------------------------------------------------------------------
__device__ __forceinline__ uint32_t s2u(const void* p) {
    uint32_t a;
    asm("{ .reg .u64 t; cvta.to.shared.u64 t, %1; cvt.u32.u64 %0, t; }"
        : "=r"(a) : "l"(p));
    return a;
}
__device__ __forceinline__ void cpasync16(uint32_t dst, const void* src) {
    asm volatile("cp.async.cg.shared.global [%0], [%1], 16;" :: "r"(dst), "l"(src));
}
#define CP_COMMIT() asm volatile("cp.async.commit_group;" ::: "memory")
#define CP_WAITN(n) asm volatile("cp.async.wait_group %0;" :: "n"(n) : "memory")

__device__ __forceinline__ void ldsm4(uint32_t* r, uint32_t addr) {
    asm volatile("ldmatrix.sync.aligned.m8n8.x4.shared.b16 {%0,%1,%2,%3}, [%4];"
                 : "=r"(r[0]), "=r"(r[1]), "=r"(r[2]), "=r"(r[3]) : "r"(addr));
}
__device__ __forceinline__ void mma16816(float* c, const uint32_t* a, uint32_t b0, uint32_t b1) {
    asm volatile("mma.sync.aligned.m16n8k16.row.col.f32.bf16.bf16.f32 "
                 "{%0,%1,%2,%3}, {%4,%5,%6,%7}, {%8,%9}, {%0,%1,%2,%3};"
                 : "+f"(c[0]), "+f"(c[1]), "+f"(c[2]), "+f"(c[3])
                 : "r"(a[0]), "r"(a[1]), "r"(a[2]), "r"(a[3]), "r"(b0), "r"(b1));
}

// ---------------------------------------------------------------------------
// 2-way split kernel
// ---------------------------------------------------------------------------
__global__ void split2_k(const float* __restrict__ s, bf16* __restrict__ o0,
                         bf16* __restrict__ o1, int n4) {
    int i = blockIdx.x * blockDim.x + threadIdx.x;
    if (i >= n4) return;
    float4 x = reinterpret_cast<const float4*>(s)[i];
    bf16 h0[4], h1[4];
#pragma unroll
    for (int e = 0; e < 4; e++) {
        float v = (&x.x)[e];
        h0[e] = __float2bfloat16(v);
        h1[e] = __float2bfloat16(v - __bfloat162float(h0[e]));
    }
    reinterpret_cast<bf162*>(o0)[i * 2]     = __halves2bfloat162(h0[0], h0[1]);
    reinterpret_cast<bf162*>(o0)[i * 2 + 1] = __halves2bfloat162(h0[2], h0[3]);
    reinterpret_cast<bf162*>(o1)[i * 2]     = __halves2bfloat162(h1[0], h1[1]);
    reinterpret_cast<bf162*>(o1)[i * 2 + 1] = __halves2bfloat162(h1[2], h1[3]);
}

// ---------------------------------------------------------------------------
// fp32 FFMA NT GEMM (roofline-proven) — Q/K projections.
// ---------------------------------------------------------------------------
__global__ __launch_bounds__(256, 2)
void gemm_nt(const float* __restrict__ A, const float* __restrict__ Bm,
             const float* __restrict__ bias, float* __restrict__ C,
             bf16* __restrict__ Cb,
             int M, int N, int K, int Lper)
{
    __shared__ float As[16][132];
    __shared__ float Bs[16][132];

    const int tid = threadIdx.x;
    const int tx = tid & 15;
    const int ty = tid >> 4;
    const int m0 = blockIdx.y * 128;
    const int n0 = blockIdx.x * 128;
    const int lrow = tid >> 1;
    const int lcol = (tid & 1) * 8;

    float acc[8][8];
#pragma unroll
    for (int i = 0; i < 8; i++)
#pragma unroll
        for (int j = 0; j < 8; j++) acc[i][j] = 0.f;

    const float* agp = A  + (size_t)(m0 + lrow) * K + lcol;
    const float* bgp = Bm + (size_t)(n0 + lrow) * K + lcol;

    float4 ra0 = *(const float4*)(agp);
    float4 ra1 = *(const float4*)(agp + 4);
    float4 rb0 = *(const float4*)(bgp);
    float4 rb1 = *(const float4*)(bgp + 4);

    for (int k0 = 0; k0 < K; k0 += 16) {
        __syncthreads();
        As[lcol + 0][lrow] = ra0.x; As[lcol + 1][lrow] = ra0.y;
        As[lcol + 2][lrow] = ra0.z; As[lcol + 3][lrow] = ra0.w;
        As[lcol + 4][lrow] = ra1.x; As[lcol + 5][lrow] = ra1.y;
        As[lcol + 6][lrow] = ra1.z; As[lcol + 7][lrow] = ra1.w;
        Bs[lcol + 0][lrow] = rb0.x; Bs[lcol + 1][lrow] = rb0.y;
        Bs[lcol + 2][lrow] = rb0.z; Bs[lcol + 3][lrow] = rb0.w;
        Bs[lcol + 4][lrow] = rb1.x; Bs[lcol + 5][lrow] = rb1.y;
        Bs[lcol + 6][lrow] = rb1.z; Bs[lcol + 7][lrow] = rb1.w;
        __syncthreads();

        if (k0 + 16 < K) {
            ra0 = *(const float4*)(agp + k0 + 16);
            ra1 = *(const float4*)(agp + k0 + 20);
            rb0 = *(const float4*)(bgp + k0 + 16);
            rb1 = *(const float4*)(bgp + k0 + 20);
        }

#pragma unroll
        for (int kk = 0; kk < 16; kk++) {
            float4 xa0 = *(const float4*)&As[kk][ty * 4];
            float4 xa1 = *(const float4*)&As[kk][64 + ty * 4];
            float4 xb0 = *(const float4*)&Bs[kk][tx * 4];
            float4 xb1 = *(const float4*)&Bs[kk][64 + tx * 4];
            float av[8], bv[8];
            av[0] = xa0.x; av[1] = xa0.y; av[2] = xa0.z; av[3] = xa0.w;
            av[4] = xa1.x; av[5] = xa1.y; av[6] = xa1.z; av[7] = xa1.w;
            bv[0] = xb0.x; bv[1] = xb0.y; bv[2] = xb0.z; bv[3] = xb0.w;
            bv[4] = xb1.x; bv[5] = xb1.y; bv[6] = xb1.z; bv[7] = xb1.w;
#pragma unroll
            for (int i = 0; i < 8; i++)
#pragma unroll
                for (int j = 0; j < 8; j++)
                    acc[i][j] = fmaf(av[i], bv[j], acc[i][j]);
        }
    }

#pragma unroll
    for (int i = 0; i < 8; i++) {
        const int m = m0 + ((i < 4) ? (ty * 4 + i) : (64 + ty * 4 + (i - 4)));
        const int bb = m / Lper;
        const int mm = m - bb * Lper;
#pragma unroll
        for (int j = 0; j < 8; j++) {
            const int n = n0 + ((j < 4) ? (tx * 4 + j) : (64 + tx * 4 + (j - 4)));
            float val = acc[i][j] + bias[n];
            const int h = n >> 6;
            const int d = n & 63;
            const size_t base = (((size_t)bb * NHEAD + h) * Lper + mm) * 64 + d;
            C[base] = val;
            Cb[base] = __float2bfloat16(val);
        }
    }
}

// ---------------------------------------------------------------------------
// 2-split bf16 HMMA projection GEMM (R13-proven).
// EPI 1: fp32 head-split (+bias) [V]; EPI 2: fp32 linear (+bias) [O].
// ---------------------------------------------------------------------------
template<int EPI>
__global__ __launch_bounds__(256, 2)
void proj_mma(const bf16* __restrict__ A0, const bf16* __restrict__ A1,
              const bf16* __restrict__ B0, const bf16* __restrict__ B1,
              const float* __restrict__ bias, float* __restrict__ co, int Lper)
{
    constexpr int K  = 1024;
    constexpr int CPP = K / 32;
    constexpr int NC = 3 * CPP;
    extern __shared__ char smem[];
    const uint32_t sb = s2u(smem);
    const int tid = threadIdx.x, lane = tid & 31, wid = tid >> 5;
    const int m0 = blockIdx.y * 128, n0 = blockIdx.x * 128;
    const int lrow = tid & 127, lseg = tid >> 7;

    const size_t abase = (size_t)(m0 + lrow) * K + lseg * 8;
    const size_t bbase2 = (size_t)(n0 + lrow) * K + lseg * 8;
    const bf16* pA0 = A0 + abase; const bf16* pA1 = A1 + abase;
    const bf16* pB0 = B0 + bbase2; const bf16* pB1 = B1 + bbase2;

    const uint32_t sa  = sb + lrow * 80 + lseg * 16;
    const uint32_t sbm = sb + 10240 + lrow * 80 + lseg * 16;

    auto issue = [&](int cc) {
        const int p = cc / CPP, kc = cc % CPP;
        const uint32_t st = (cc % 3) * 20480;
        const bf16* ag = (p == 1) ? pA1 : pA0;
        const bf16* bg = (p == 0) ? pB1 : pB0;
        ag += kc * 32; bg += kc * 32;
        cpasync16(sa + st,       ag);
        cpasync16(sa + st + 32,  ag + 16);
        cpasync16(sbm + st,      bg);
        cpasync16(sbm + st + 32, bg + 16);
    };

    issue(0); CP_COMMIT();
    issue(1); CP_COMMIT();

    const int wm = (wid & 1) * 64, wn = (wid >> 1) * 32;
    uint32_t aoff[4], boff[2];
#pragma unroll
    for (int mt = 0; mt < 4; mt++)
        aoff[mt] = (wm + mt * 16 + (lane & 15)) * 80 + (lane >> 4) * 16;
#pragma unroll
    for (int ng = 0; ng < 2; ng++)
        boff[ng] = 10240 + (wn + ng * 16 + (lane & 15)) * 80 + (lane >> 4) * 16;

    float c[4][4][4];
#pragma unroll
    for (int i = 0; i < 4; i++)
#pragma unroll
        for (int j = 0; j < 4; j++)
#pragma unroll
            for (int e = 0; e < 4; e++) c[i][j][e] = 0.f;

#pragma unroll 1
    for (int cc = 0; cc < NC; cc++) {
        CP_WAITN(1);
        __syncthreads();
        if (cc + 2 < NC) issue(cc + 2);
        CP_COMMIT();
        const uint32_t st = sb + (cc % 3) * 20480;
#pragma unroll
        for (int ks = 0; ks < 2; ks++) {
            uint32_t af[4][4], bfr[2][4];
#pragma unroll
            for (int mt = 0; mt < 4; mt++) ldsm4(af[mt], st + aoff[mt] + ks * 32);
#pragma unroll
            for (int ng = 0; ng < 2; ng++) ldsm4(bfr[ng], st + boff[ng] + ks * 32);
#pragma unroll
            for (int mt = 0; mt < 4; mt++)
#pragma unroll
                for (int nt = 0; nt < 4; nt++)
                    mma16816(c[mt][nt], af[mt],
                             bfr[nt >> 1][nt & 1], bfr[nt >> 1][(nt & 1) + 2]);
        }
    }

#pragma unroll
    for (int mt = 0; mt < 4; mt++) {
#pragma unroll
        for (int half = 0; half < 2; half++) {
            const int m = m0 + wm + mt * 16 + (lane >> 2) + half * 8;
            int bb = 0, mm = m;
            if (EPI == 1) { bb = m / Lper; mm = m - bb * Lper; }
#pragma unroll
            for (int nt = 0; nt < 4; nt++) {
                const int n = n0 + wn + nt * 8 + (lane & 3) * 2;
                const float2 bv = *reinterpret_cast<const float2*>(bias + n);
                float2 fv;
                fv.x = c[mt][nt][half * 2 + 0] + bv.x;
                fv.y = c[mt][nt][half * 2 + 1] + bv.y;
                if (EPI == 2) {
                    *reinterpret_cast<float2*>(co + (size_t)m * HID + n) = fv;
                } else {
                    const int h = n >> 6, d = n & 63;
                    *reinterpret_cast<float2*>(
                        co + (((size_t)bb * NHEAD + h) * Lper + mm) * 64 + d) = fv;
                }
            }
        }
    }
}

// ---------------------------------------------------------------------------
// bf16 HMMA filter-scores GEMM (R8-proven, whole-BH grid z).
// ---------------------------------------------------------------------------
__global__ __launch_bounds__(512, 2)
void score_bf16(const bf16* __restrict__ Qb, const bf16* __restrict__ Kb,
                bf16* __restrict__ sc)
{
    extern __shared__ char smem[];
    const uint32_t sb = s2u(smem);
    const int tid = threadIdx.x, lane = tid & 31, wid = tid >> 5;
    const int n0 = blockIdx.x * 128;
    const int m0 = blockIdx.y * 128;
    const int z = blockIdx.z;

    const int lrow = tid >> 1;
    const int lseg = tid & 1;
    const bool isA = lrow < 128;
    const int grow = isA ? (m0 + lrow) : (n0 + lrow - 128);
    const bf16* gp = (isA ? Qb + (size_t)z * QLEN * 64 : Kb + (size_t)z * KVLEN * 64)
                     + (size_t)grow * 64 + lseg * 8;
    const uint32_t swr = sb + lrow * 80 + lseg * 16;

#pragma unroll
    for (int cc = 0; cc < 2; cc++) {
        const bf16* g = gp + cc * 32;
        cpasync16(swr + cc * 20480,      g);
        cpasync16(swr + cc * 20480 + 32, g + 16);
        CP_COMMIT();
    }

    const int wm = (wid & 1) * 64, wn = (wid >> 1) * 16;
    uint32_t aoff[4];
#pragma unroll
    for (int mt = 0; mt < 4; mt++)
        aoff[mt] = (wm + mt * 16 + (lane & 15)) * 80 + (lane >> 4) * 16;
    const uint32_t boff = 10240 + (wn + (lane & 15)) * 80 + (lane >> 4) * 16;

    float c[4][2][4];
#pragma unroll
    for (int i = 0; i < 4; i++)
#pragma unroll
        for (int j = 0; j < 2; j++)
#pragma unroll
            for (int e = 0; e < 4; e++) c[i][j][e] = 0.f;

    CP_WAITN(1);
    __syncthreads();
#pragma unroll
    for (int cc = 0; cc < 2; cc++) {
        if (cc == 1) { CP_WAITN(0); __syncthreads(); }
        const uint32_t st = sb + cc * 20480;
#pragma unroll
        for (int ks = 0; ks < 2; ks++) {
            uint32_t af[4][4], bfr[4];
#pragma unroll
            for (int mt = 0; mt < 4; mt++) ldsm4(af[mt], st + aoff[mt] + ks * 32);
            ldsm4(bfr, st + boff + ks * 32);
#pragma unroll
            for (int mt = 0; mt < 4; mt++)
#pragma unroll
                for (int nt = 0; nt < 2; nt++)
                    mma16816(c[mt][nt], af[mt], bfr[nt], bfr[nt + 2]);
        }
    }

#pragma unroll
    for (int mt = 0; mt < 4; mt++) {
#pragma unroll
        for (int half = 0; half < 2; half++) {
            const int m = m0 + wm + mt * 16 + (lane >> 2) + half * 8;
            bf16* dst = sc + ((size_t)z * QLEN + m) * KVLEN;
#pragma unroll
            for (int nt = 0; nt < 2; nt++) {
                const int n = n0 + wn + nt * 8 + (lane & 3) * 2;
                bf162 v = __halves2bfloat162(
                    __float2bfloat16(c[mt][nt][half * 2 + 0] * 0.125f),
                    __float2bfloat16(c[mt][nt][half * 2 + 1] * 0.125f));
                *reinterpret_cast<bf162*>(dst + n) = v;
            }
        }
    }
}

// ---------------------------------------------------------------------------
// Warp reductions
// ---------------------------------------------------------------------------
__device__ __forceinline__ float warp_min(float v) {
#pragma unroll
    for (int o = 16; o; o >>= 1) v = fminf(v, __shfl_xor_sync(FULLMASK, v, o));
    return v;
}
__device__ __forceinline__ float warp_max(float v) {
#pragma unroll
    for (int o = 16; o; o >>= 1) v = fmaxf(v, __shfl_xor_sync(FULLMASK, v, o));
    return v;
}
__device__ __forceinline__ float warp_sum(float v) {
#pragma unroll
    for (int o = 16; o; o >>= 1) v += __shfl_xor_sync(FULLMASK, v, o);
    return v;
}
__device__ __forceinline__ void warp_argmin(float v, int idx, float& mv, int& ml) {
    mv = v; ml = idx;
#pragma unroll
    for (int o = 16; o; o >>= 1) {
        const float ov = __shfl_xor_sync(FULLMASK, mv, o);
        const int   ol = __shfl_xor_sync(FULLMASK, ml, o);
        if (ov < mv || (ov == mv && ol < ml)) { mv = ov; ml = ol; }
    }
}

// ---------------------------------------------------------------------------
// Top-k (R13 body + ONE change: hmax2 packet guard in phase 1 — skips the
// 8 scalar compares when no packet value can beat the lane's TK-th best.
// Guard false => no value passes cv > tb[TK-1] => candidate set identical.)
// ---------------------------------------------------------------------------
__global__ __launch_bounds__(256)
void topk_attend(const bf16* __restrict__ scb,
                 const float* __restrict__ qf, const float* __restrict__ kf,
                 const float* __restrict__ v,
                 bf16* __restrict__ a0out, bf16* __restrict__ a1out)
{
    __shared__ float qs[8][64];

    const int wlocal = threadIdx.x >> 5;
    const int gwarp = (blockIdx.x * blockDim.x + threadIdx.x) >> 5;
    const int lane = threadIdx.x & 31;
    if (gwarp >= BH * QLEN) return;

    const int m = gwarp % QLEN;
    const int h = (gwarp / QLEN) % NHEAD;
    const int b = gwarp / (QLEN * NHEAD);
    const size_t bh = (size_t)b * NHEAD + h;

    // ---- phase 1: lane-private top-TK with packet max-prune ----
    float tb[TK]; int ib[TK];
#pragma unroll
    for (int j = 0; j < TK; j++) { tb[j] = -INFINITY; ib[j] = 0; }

    const uint4* srow = reinterpret_cast<const uint4*>(scb + (size_t)gwarp * KVLEN);
#pragma unroll 1
    for (int c = 0; c < 16; c++) {
        const uint4 pk = srow[c * 32 + lane];
        const int base = (c * 32 + lane) * 8;
        const uint32_t ws[4] = {pk.x, pk.y, pk.z, pk.w};
        // packet max (8 bf16) via hmax2 tree — 4 ops
        const bf162 b0 = *reinterpret_cast<const bf162*>(&ws[0]);
        const bf162 b1 = *reinterpret_cast<const bf162*>(&ws[1]);
        const bf162 b2 = *reinterpret_cast<const bf162*>(&ws[2]);
        const bf162 b3 = *reinterpret_cast<const bf162*>(&ws[3]);
        const bf162 mm01 = __hmax2(b0, b1);
        const bf162 mm23 = __hmax2(b2, b3);
        const bf162 mm8 = __hmax2(mm01, mm23);
        const float m8 = fmaxf(__low2float(mm8), __high2float(mm8));
        if (m8 <= tb[TK - 1]) continue;   // nothing here can enter the list
#pragma unroll
        for (int e = 0; e < 4; e++) {
            const bf162 pr = *reinterpret_cast<const bf162*>(&ws[e]);
            const float v0 = __low2float(pr);
            const float v1 = __high2float(pr);
#pragma unroll
            for (int half = 0; half < 2; half++) {
                float cv = half ? v1 : v0;
                int ci = base + e * 2 + half;
                if (cv > tb[TK - 1]) {
#pragma unroll
                    for (int j = 0; j < TK; j++) {
                        if (cv > tb[j]) {
                            const float tv = tb[j]; const int tx2 = ib[j];
                            tb[j] = cv; ib[j] = ci; cv = tv; ci = tx2;
                        }
                    }
                }
            }
        }
    }

    const float tau = warp_min(tb[1]) - 0.02f;

    // ---- phase 2: exact sequential-fp32 rescore of candidates >= tau ----
    {
        const float* qrow = qf + (bh * QLEN + m) * 64;
        if (lane < 16)
            *reinterpret_cast<float4*>(&qs[wlocal][lane * 4]) =
                *reinterpret_cast<const float4*>(qrow + lane * 4);
        __syncwarp();
    }
    const float* kbase = kf + bh * KVLEN * 64;
    float es[TK];
#pragma unroll
    for (int j = 0; j < TK; j++) {
        es[j] = -INFINITY;
        if (tb[j] >= tau) {
            const float* kr = kbase + (size_t)ib[j] * 64;
            float acc = 0.f;
#pragma unroll
            for (int t = 0; t < 16; t++) {
                const float4 k4 = *reinterpret_cast<const float4*>(kr + t * 4);
                const float4 q4 = *reinterpret_cast<const float4*>(&qs[wlocal][t * 4]);
                acc = fmaf(q4.x, k4.x, acc);
                acc = fmaf(q4.y, k4.y, acc);
                acc = fmaf(q4.z, k4.z, acc);
                acc = fmaf(q4.w, k4.w, acc);
            }
            es[j] = acc * 0.125f;
        }
    }

    // ---- phase 3: merge per-lane rounds into warp-wide exact top-32 ----
    float ls = es[0];
    int   li = ib[0];
#pragma unroll
    for (int r = 1; r < TK; r++) {
        const float cnd = es[r];
        const int cidx = ib[r];
        const float curmin = warp_min(ls);
        unsigned mask = __ballot_sync(FULLMASK, cnd > curmin);
        while (mask) {
            const int src = __ffs(mask) - 1;
            mask &= mask - 1;
            const float cand = __shfl_sync(FULLMASK, cnd, src);
            float mv; int ml;
            warp_argmin(ls, lane, mv, ml);
            if (cand > mv) {
                const int candidx = __shfl_sync(FULLMASK, cidx, src);
                if (lane == ml) { ls = cand; li = candidx; }
            }
        }
    }

    // ---- softmax on exact scores + V gather ----
    const float mx = warp_max(ls);
    float w = expf(ls - mx);
    const float Z = warp_sum(w);
    w /= Z;

    const float* vb = v + bh * KVLEN * 64;
    float a0 = 0.f, a1 = 0.f;
#pragma unroll
    for (int e = 0; e < TOPK; e++) {
        const float we = __shfl_sync(FULLMASK, w, e);
        const int   ie = __shfl_sync(FULLMASK, li, e);
        const float* vr = vb + (size_t)ie * 64;
        a0 = fmaf(we, vr[lane], a0);
        a1 = fmaf(we, vr[lane + 32], a1);
    }

    const size_t dst = ((size_t)b * QLEN + m) * HID + h * 64;
    bf16 pl0 = __float2bfloat16(a0);
    bf16 pl1 = __float2bfloat16(a1);
    a0out[dst + lane]      = pl0;
    a0out[dst + lane + 32] = pl1;
    a1out[dst + lane]      = __float2bfloat16(a0 - __bfloat162float(pl0));
    a1out[dst + lane + 32] = __float2bfloat16(a1 - __bfloat162float(pl1));
}

// ---------------------------------------------------------------------------
// Host launcher (R13 layout: single main stream + V side stream)
// ---------------------------------------------------------------------------
extern "C" void kernel_launch(void* const* d_in, const int* in_sizes, int n_in,
                              void* d_out, int out_size)
{
    const float* query = (const float*)d_in[0];
    const float* key   = (const float*)d_in[1];
    const float* value = (const float*)d_in[2];
    const float* Wq = (const float*)d_in[3];
    const float* bq = (const float*)d_in[4];
    const float* Wk = (const float*)d_in[5];
    const float* bk = (const float*)d_in[6];
    const float* Wv = (const float*)d_in[7];
    const float* bv = (const float*)d_in[8];
    const float* Wo = (const float*)d_in[9];
    const float* bo = (const float*)d_in[10];
    float* out = (float*)d_out;

    float *q, *k, *v;
    bf16 *qb, *kb, *scb, *vs0, *vs1, *wv0, *wv1, *wo0, *wo1, *at0, *at1;
    cudaGetSymbolAddress((void**)&q, g_q);
    cudaGetSymbolAddress((void**)&k, g_k);
    cudaGetSymbolAddress((void**)&v, g_v);
    cudaGetSymbolAddress((void**)&qb, g_qb);
    cudaGetSymbolAddress((void**)&kb, g_kb);
    cudaGetSymbolAddress((void**)&scb, g_scb);
    cudaGetSymbolAddress((void**)&vs0, g_vs0);
    cudaGetSymbolAddress((void**)&vs1, g_vs1);
    cudaGetSymbolAddress((void**)&wv0, g_wv0);
    cudaGetSymbolAddress((void**)&wv1, g_wv1);
    cudaGetSymbolAddress((void**)&wo0, g_wo0);
    cudaGetSymbolAddress((void**)&wo1, g_wo1);
    cudaGetSymbolAddress((void**)&at0, g_at0);
    cudaGetSymbolAddress((void**)&at1, g_at1);

    const int SSM = 2 * 20480;
    const int PSM = 3 * 20480;
    cudaFuncSetAttribute(score_bf16, cudaFuncAttributeMaxDynamicSharedMemorySize, SSM);
    cudaFuncSetAttribute(proj_mma<1>, cudaFuncAttributeMaxDynamicSharedMemorySize, PSM);
    cudaFuncSetAttribute(proj_mma<2>, cudaFuncAttributeMaxDynamicSharedMemorySize, PSM);

    static cudaStream_t s_v = nullptr;
    static cudaEvent_t ev_fork = nullptr, ev_join = nullptr;
    if (!s_v) {
        cudaStreamCreateWithFlags(&s_v, cudaStreamNonBlocking);
        cudaEventCreateWithFlags(&ev_fork, cudaEventDisableTiming);
        cudaEventCreateWithFlags(&ev_join, cudaEventDisableTiming);
    }

    const dim3 blk(256);

    // fork side stream
    cudaEventRecord(ev_fork, 0);
    cudaStreamWaitEvent(s_v, ev_fork, 0);

    // side stream: split value + Wv, then V projection (HMMA 2-split)
    split2_k<<<(MKV * HID / 4 + 255) / 256, 256, 0, s_v>>>(value, vs0, vs1, MKV * HID / 4);
    split2_k<<<(HID * HID / 4 + 255) / 256, 256, 0, s_v>>>(Wv, wv0, wv1, HID * HID / 4);
    proj_mma<1><<<dim3(8, MKV / 128), blk, PSM, s_v>>>(vs0, vs1, wv0, wv1, bv, v, KVLEN);
    cudaEventRecord(ev_join, s_v);

    // main stream: split Wo; Q proj; K proj; filter scores
    split2_k<<<(HID * HID / 4 + 255) / 256, 256>>>(Wo, wo0, wo1, HID * HID / 4);

    gemm_nt<<<dim3(HID / 128, MQ / 128), blk>>>(
        query, Wq, bq, q, qb, MQ, HID, HID, QLEN);

    gemm_nt<<<dim3(HID / 128, MKV / 128), blk>>>(
        key, Wk, bk, k, kb, MKV, HID, HID, KVLEN);

    score_bf16<<<dim3(KVLEN / 128, QLEN / 128, BH), 512, SSM>>>(qb, kb, scb);

    // join: topk needs v
    cudaStreamWaitEvent(0, ev_join, 0);

    // Top-k: packet-pruned lane-local filter + exact rescore + softmax + gather
    topk_attend<<<(BH * QLEN) / 8, blk>>>(scb, q, k, v, at0, at1);

    // Output projection (HMMA 2-split) -> d_out
    proj_mma<2><<<dim3(8, MQ / 128), blk, PSM>>>(at0, at1, wo0, wo1, bo, out, 0);
}

// round 17
// speedup vs baseline: 1.1865x; 1.1865x over previous
#include <cuda_runtime.h>
#include <cuda_bf16.h>
#include <math.h>
#include <stdint.h>

#define FULLMASK 0xffffffffu
#define BATCH 2
#define NHEAD 16
#define KVLEN 4096
#define QLEN  2048
#define HDIM  64
#define HID   1024
#define TOPK  32
#define BH    (BATCH * NHEAD)
#define TK    10
#define MQ    (BATCH * QLEN)
#define MKV   (BATCH * KVLEN)

typedef __nv_bfloat16 bf16;
typedef __nv_bfloat162 bf162;

// ---------------------------------------------------------------------------
// Scratch
// ---------------------------------------------------------------------------
__device__ float g_q[(size_t)BH * QLEN * HDIM];
__device__ float g_k[(size_t)BH * KVLEN * HDIM];
__device__ float g_v[(size_t)BH * KVLEN * HDIM];
__device__ bf16  g_qb[(size_t)BH * QLEN * HDIM];
__device__ bf16  g_kb[(size_t)BH * KVLEN * HDIM];
__device__ bf16  g_scb[(size_t)BH * QLEN * KVLEN];
__device__ bf16  g_vs0[(size_t)MKV * HID], g_vs1[(size_t)MKV * HID];
__device__ bf16  g_wv0[(size_t)HID * HID], g_wv1[(size_t)HID * HID];
__device__ bf16  g_wo0[(size_t)HID * HID], g_wo1[(size_t)HID * HID];
__device__ bf16  g_at0[(size_t)MQ * HID],  g_at1[(size_t)MQ * HID];

// ---------------------------------------------------------------------------
// PTX helpers (sm_80 baseline)
// ---------------------------------------------------------------------------
__device__ __forceinline__ uint32_t s2u(const void* p) {
    uint32_t a;
    asm("{ .reg .u64 t; cvta.to.shared.u64 t, %1; cvt.u32.u64 %0, t; }"
        : "=r"(a) : "l"(p));
    return a;
}
__device__ __forceinline__ void cpasync16(uint32_t dst, const void* src) {
    asm volatile("cp.async.cg.shared.global [%0], [%1], 16;" :: "r"(dst), "l"(src));
}
#define CP_COMMIT() asm volatile("cp.async.commit_group;" ::: "memory")
#define CP_WAITN(n) asm volatile("cp.async.wait_group %0;" :: "n"(n) : "memory")

__device__ __forceinline__ void ldsm4(uint32_t* r, uint32_t addr) {
    asm volatile("ldmatrix.sync.aligned.m8n8.x4.shared.b16 {%0,%1,%2,%3}, [%4];"
                 : "=r"(r[0]), "=r"(r[1]), "=r"(r[2]), "=r"(r[3]) : "r"(addr));
}
__device__ __forceinline__ void mma16816(float* c, const uint32_t* a, uint32_t b0, uint32_t b1) {
    asm volatile("mma.sync.aligned.m16n8k16.row.col.f32.bf16.bf16.f32 "
                 "{%0,%1,%2,%3}, {%4,%5,%6,%7}, {%8,%9}, {%0,%1,%2,%3};"
                 : "+f"(c[0]), "+f"(c[1]), "+f"(c[2]), "+f"(c[3])
                 : "r"(a[0]), "r"(a[1]), "r"(a[2]), "r"(a[3]), "r"(b0), "r"(b1));
}

// ---------------------------------------------------------------------------
// 2-way split kernel
// ---------------------------------------------------------------------------
__global__ void split2_k(const float* __restrict__ s, bf16* __restrict__ o0,
                         bf16* __restrict__ o1, int n4) {
    int i = blockIdx.x * blockDim.x + threadIdx.x;
    if (i >= n4) return;
    float4 x = reinterpret_cast<const float4*>(s)[i];
    bf16 h0[4], h1[4];
#pragma unroll
    for (int e = 0; e < 4; e++) {
        float v = (&x.x)[e];
        h0[e] = __float2bfloat16(v);
        h1[e] = __float2bfloat16(v - __bfloat162float(h0[e]));
    }
    reinterpret_cast<bf162*>(o0)[i * 2]     = __halves2bfloat162(h0[0], h0[1]);
    reinterpret_cast<bf162*>(o0)[i * 2 + 1] = __halves2bfloat162(h0[2], h0[3]);
    reinterpret_cast<bf162*>(o1)[i * 2]     = __halves2bfloat162(h1[0], h1[1]);
    reinterpret_cast<bf162*>(o1)[i * 2 + 1] = __halves2bfloat162(h1[2], h1[3]);
}

// ---------------------------------------------------------------------------
// Fused Q+K fp32 FFMA NT projection (R13 gemm_nt body; blockIdx.y dispatches
// Q-rows [0, MQ/128) vs K-rows [MQ/128, MQ/128+MKV/128) — per-row arithmetic
// identical to the two separate launches; one grid fills waves better).
// ---------------------------------------------------------------------------
__global__ __launch_bounds__(256, 2)
void gemm_qk_fused(const float* __restrict__ Aq, const float* __restrict__ Wq,
                   const float* __restrict__ bq,
                   const float* __restrict__ Ak, const float* __restrict__ Wk,
                   const float* __restrict__ bk,
                   float* __restrict__ Cq, bf16* __restrict__ Cqb,
                   float* __restrict__ Ck, bf16* __restrict__ Ckb)
{
    __shared__ float As[16][132];
    __shared__ float Bs[16][132];

    const int tid = threadIdx.x;
    const int tx = tid & 15;
    const int ty = tid >> 4;

    const bool isQ = (blockIdx.y < (MQ / 128));
    const int m0 = (isQ ? blockIdx.y : blockIdx.y - MQ / 128) * 128;
    const int n0 = blockIdx.x * 128;
    const int Lper = isQ ? QLEN : KVLEN;
    const float* A    = isQ ? Aq : Ak;
    const float* Bm   = isQ ? Wq : Wk;
    const float* bias = isQ ? bq : bk;
    float* C  = isQ ? Cq : Ck;
    bf16*  Cb = isQ ? Cqb : Ckb;

    const int lrow = tid >> 1;
    const int lcol = (tid & 1) * 8;

    float acc[8][8];
#pragma unroll
    for (int i = 0; i < 8; i++)
#pragma unroll
        for (int j = 0; j < 8; j++) acc[i][j] = 0.f;

    const float* agp = A  + (size_t)(m0 + lrow) * HID + lcol;
    const float* bgp = Bm + (size_t)(n0 + lrow) * HID + lcol;

    float4 ra0 = *(const float4*)(agp);
    float4 ra1 = *(const float4*)(agp + 4);
    float4 rb0 = *(const float4*)(bgp);
    float4 rb1 = *(const float4*)(bgp + 4);

    for (int k0 = 0; k0 < HID; k0 += 16) {
        __syncthreads();
        As[lcol + 0][lrow] = ra0.x; As[lcol + 1][lrow] = ra0.y;
        As[lcol + 2][lrow] = ra0.z; As[lcol + 3][lrow] = ra0.w;
        As[lcol + 4][lrow] = ra1.x; As[lcol + 5][lrow] = ra1.y;
        As[lcol + 6][lrow] = ra1.z; As[lcol + 7][lrow] = ra1.w;
        Bs[lcol + 0][lrow] = rb0.x; Bs[lcol + 1][lrow] = rb0.y;
        Bs[lcol + 2][lrow] = rb0.z; Bs[lcol + 3][lrow] = rb0.w;
        Bs[lcol + 4][lrow] = rb1.x; Bs[lcol + 5][lrow] = rb1.y;
        Bs[lcol + 6][lrow] = rb1.z; Bs[lcol + 7][lrow] = rb1.w;
        __syncthreads();

        if (k0 + 16 < HID) {
            ra0 = *(const float4*)(agp + k0 + 16);
            ra1 = *(const float4*)(agp + k0 + 20);
            rb0 = *(const float4*)(bgp + k0 + 16);
            rb1 = *(const float4*)(bgp + k0 + 20);
        }

#pragma unroll
        for (int kk = 0; kk < 16; kk++) {
            float4 xa0 = *(const float4*)&As[kk][ty * 4];
            float4 xa1 = *(const float4*)&As[kk][64 + ty * 4];
            float4 xb0 = *(const float4*)&Bs[kk][tx * 4];
            float4 xb1 = *(const float4*)&Bs[kk][64 + tx * 4];
            float av[8], bv[8];
            av[0] = xa0.x; av[1] = xa0.y; av[2] = xa0.z; av[3] = xa0.w;
            av[4] = xa1.x; av[5] = xa1.y; av[6] = xa1.z; av[7] = xa1.w;
            bv[0] = xb0.x; bv[1] = xb0.y; bv[2] = xb0.z; bv[3] = xb0.w;
            bv[4] = xb1.x; bv[5] = xb1.y; bv[6] = xb1.z; bv[7] = xb1.w;
#pragma unroll
            for (int i = 0; i < 8; i++)
#pragma unroll
                for (int j = 0; j < 8; j++)
                    acc[i][j] = fmaf(av[i], bv[j], acc[i][j]);
        }
    }

#pragma unroll
    for (int i = 0; i < 8; i++) {
        const int m = m0 + ((i < 4) ? (ty * 4 + i) : (64 + ty * 4 + (i - 4)));
        const int bb = m / Lper;
        const int mm = m - bb * Lper;
#pragma unroll
        for (int j = 0; j < 8; j++) {
            const int n = n0 + ((j < 4) ? (tx * 4 + j) : (64 + tx * 4 + (j - 4)));
            float val = acc[i][j] + bias[n];
            const int h = n >> 6;
            const int d = n & 63;
            const size_t base = (((size_t)bb * NHEAD + h) * Lper + mm) * 64 + d;
            C[base] = val;
            Cb[base] = __float2bfloat16(val);
        }
    }
}

// ---------------------------------------------------------------------------
// 2-split bf16 HMMA projection GEMM (R13-proven).
// EPI 1: fp32 head-split (+bias) [V]; EPI 2: fp32 linear (+bias) [O].
// ---------------------------------------------------------------------------
template<int EPI>
__global__ __launch_bounds__(256, 2)
void proj_mma(const bf16* __restrict__ A0, const bf16* __restrict__ A1,
              const bf16* __restrict__ B0, const bf16* __restrict__ B1,
              const float* __restrict__ bias, float* __restrict__ co, int Lper)
{
    constexpr int K  = 1024;
    constexpr int CPP = K / 32;
    constexpr int NC = 3 * CPP;
    extern __shared__ char smem[];
    const uint32_t sb = s2u(smem);
    const int tid = threadIdx.x, lane = tid & 31, wid = tid >> 5;
    const int m0 = blockIdx.y * 128, n0 = blockIdx.x * 128;
    const int lrow = tid & 127, lseg = tid >> 7;

    const size_t abase = (size_t)(m0 + lrow) * K + lseg * 8;
    const size_t bbase2 = (size_t)(n0 + lrow) * K + lseg * 8;
    const bf16* pA0 = A0 + abase; const bf16* pA1 = A1 + abase;
    const bf16* pB0 = B0 + bbase2; const bf16* pB1 = B1 + bbase2;

    const uint32_t sa  = sb + lrow * 80 + lseg * 16;
    const uint32_t sbm = sb + 10240 + lrow * 80 + lseg * 16;

    auto issue = [&](int cc) {
        const int p = cc / CPP, kc = cc % CPP;
        const uint32_t st = (cc % 3) * 20480;
        const bf16* ag = (p == 1) ? pA1 : pA0;
        const bf16* bg = (p == 0) ? pB1 : pB0;
        ag += kc * 32; bg += kc * 32;
        cpasync16(sa + st,       ag);
        cpasync16(sa + st + 32,  ag + 16);
        cpasync16(sbm + st,      bg);
        cpasync16(sbm + st + 32, bg + 16);
    };

    issue(0); CP_COMMIT();
    issue(1); CP_COMMIT();

    const int wm = (wid & 1) * 64, wn = (wid >> 1) * 32;
    uint32_t aoff[4], boff[2];
#pragma unroll
    for (int mt = 0; mt < 4; mt++)
        aoff[mt] = (wm + mt * 16 + (lane & 15)) * 80 + (lane >> 4) * 16;
#pragma unroll
    for (int ng = 0; ng < 2; ng++)
        boff[ng] = 10240 + (wn + ng * 16 + (lane & 15)) * 80 + (lane >> 4) * 16;

    float c[4][4][4];
#pragma unroll
    for (int i = 0; i < 4; i++)
#pragma unroll
        for (int j = 0; j < 4; j++)
#pragma unroll
            for (int e = 0; e < 4; e++) c[i][j][e] = 0.f;

#pragma unroll 1
    for (int cc = 0; cc < NC; cc++) {
        CP_WAITN(1);
        __syncthreads();
        if (cc + 2 < NC) issue(cc + 2);
        CP_COMMIT();
        const uint32_t st = sb + (cc % 3) * 20480;
#pragma unroll
        for (int ks = 0; ks < 2; ks++) {
            uint32_t af[4][4], bfr[2][4];
#pragma unroll
            for (int mt = 0; mt < 4; mt++) ldsm4(af[mt], st + aoff[mt] + ks * 32);
#pragma unroll
            for (int ng = 0; ng < 2; ng++) ldsm4(bfr[ng], st + boff[ng] + ks * 32);
#pragma unroll
            for (int mt = 0; mt < 4; mt++)
#pragma unroll
                for (int nt = 0; nt < 4; nt++)
                    mma16816(c[mt][nt], af[mt],
                             bfr[nt >> 1][nt & 1], bfr[nt >> 1][(nt & 1) + 2]);
        }
    }

#pragma unroll
    for (int mt = 0; mt < 4; mt++) {
#pragma unroll
        for (int half = 0; half < 2; half++) {
            const int m = m0 + wm + mt * 16 + (lane >> 2) + half * 8;
            int bb = 0, mm = m;
            if (EPI == 1) { bb = m / Lper; mm = m - bb * Lper; }
#pragma unroll
            for (int nt = 0; nt < 4; nt++) {
                const int n = n0 + wn + nt * 8 + (lane & 3) * 2;
                const float2 bv = *reinterpret_cast<const float2*>(bias + n);
                float2 fv;
                fv.x = c[mt][nt][half * 2 + 0] + bv.x;
                fv.y = c[mt][nt][half * 2 + 1] + bv.y;
                if (EPI == 2) {
                    *reinterpret_cast<float2*>(co + (size_t)m * HID + n) = fv;
                } else {
                    const int h = n >> 6, d = n & 63;
                    *reinterpret_cast<float2*>(
                        co + (((size_t)bb * NHEAD + h) * Lper + mm) * 64 + d) = fv;
                }
            }
        }
    }
}

// ---------------------------------------------------------------------------
// bf16 HMMA filter-scores GEMM (R8-proven, whole-BH grid z).
// ---------------------------------------------------------------------------
__global__ __launch_bounds__(512, 2)
void score_bf16(const bf16* __restrict__ Qb, const bf16* __restrict__ Kb,
                bf16* __restrict__ sc)
{
    extern __shared__ char smem[];
    const uint32_t sb = s2u(smem);
    const int tid = threadIdx.x, lane = tid & 31, wid = tid >> 5;
    const int n0 = blockIdx.x * 128;
    const int m0 = blockIdx.y * 128;
    const int z = blockIdx.z;

    const int lrow = tid >> 1;
    const int lseg = tid & 1;
    const bool isA = lrow < 128;
    const int grow = isA ? (m0 + lrow) : (n0 + lrow - 128);
    const bf16* gp = (isA ? Qb + (size_t)z * QLEN * 64 : Kb + (size_t)z * KVLEN * 64)
                     + (size_t)grow * 64 + lseg * 8;
    const uint32_t swr = sb + lrow * 80 + lseg * 16;

#pragma unroll
    for (int cc = 0; cc < 2; cc++) {
        const bf16* g = gp + cc * 32;
        cpasync16(swr + cc * 20480,      g);
        cpasync16(swr + cc * 20480 + 32, g + 16);
        CP_COMMIT();
    }

    const int wm = (wid & 1) * 64, wn = (wid >> 1) * 16;
    uint32_t aoff[4];
#pragma unroll
    for (int mt = 0; mt < 4; mt++)
        aoff[mt] = (wm + mt * 16 + (lane & 15)) * 80 + (lane >> 4) * 16;
    const uint32_t boff = 10240 + (wn + (lane & 15)) * 80 + (lane >> 4) * 16;

    float c[4][2][4];
#pragma unroll
    for (int i = 0; i < 4; i++)
#pragma unroll
        for (int j = 0; j < 2; j++)
#pragma unroll
            for (int e = 0; e < 4; e++) c[i][j][e] = 0.f;

    CP_WAITN(1);
    __syncthreads();
#pragma unroll
    for (int cc = 0; cc < 2; cc++) {
        if (cc == 1) { CP_WAITN(0); __syncthreads(); }
        const uint32_t st = sb + cc * 20480;
#pragma unroll
        for (int ks = 0; ks < 2; ks++) {
            uint32_t af[4][4], bfr[4];
#pragma unroll
            for (int mt = 0; mt < 4; mt++) ldsm4(af[mt], st + aoff[mt] + ks * 32);
            ldsm4(bfr, st + boff + ks * 32);
#pragma unroll
            for (int mt = 0; mt < 4; mt++)
#pragma unroll
                for (int nt = 0; nt < 2; nt++)
                    mma16816(c[mt][nt], af[mt], bfr[nt], bfr[nt + 2]);
        }
    }

#pragma unroll
    for (int mt = 0; mt < 4; mt++) {
#pragma unroll
        for (int half = 0; half < 2; half++) {
            const int m = m0 + wm + mt * 16 + (lane >> 2) + half * 8;
            bf16* dst = sc + ((size_t)z * QLEN + m) * KVLEN;
#pragma unroll
            for (int nt = 0; nt < 2; nt++) {
                const int n = n0 + wn + nt * 8 + (lane & 3) * 2;
                bf162 v = __halves2bfloat162(
                    __float2bfloat16(c[mt][nt][half * 2 + 0] * 0.125f),
                    __float2bfloat16(c[mt][nt][half * 2 + 1] * 0.125f));
                *reinterpret_cast<bf162*>(dst + n) = v;
            }
        }
    }
}

// ---------------------------------------------------------------------------
// Warp reductions
// ---------------------------------------------------------------------------
__device__ __forceinline__ float warp_min(float v) {
#pragma unroll
    for (int o = 16; o; o >>= 1) v = fminf(v, __shfl_xor_sync(FULLMASK, v, o));
    return v;
}
__device__ __forceinline__ float warp_max(float v) {
#pragma unroll
    for (int o = 16; o; o >>= 1) v = fmaxf(v, __shfl_xor_sync(FULLMASK, v, o));
    return v;
}
__device__ __forceinline__ float warp_sum(float v) {
#pragma unroll
    for (int o = 16; o; o >>= 1) v += __shfl_xor_sync(FULLMASK, v, o);
    return v;
}
__device__ __forceinline__ void warp_argmin(float v, int idx, float& mv, int& ml) {
    mv = v; ml = idx;
#pragma unroll
    for (int o = 16; o; o >>= 1) {
        const float ov = __shfl_xor_sync(FULLMASK, mv, o);
        const int   ol = __shfl_xor_sync(FULLMASK, ml, o);
        if (ov < mv || (ov == mv && ol < ml)) { mv = ov; ml = ol; }
    }
}

// ---------------------------------------------------------------------------
// Top-k (R13 body, FROZEN): lane-private top-TK scan -> tau -> exact
// sequential-fp32 rescore -> warp merge -> softmax -> V gather ->
// 2-split bf16 attn output.
// ---------------------------------------------------------------------------
__global__ __launch_bounds__(256)
void topk_attend(const bf16* __restrict__ scb,
                 const float* __restrict__ qf, const float* __restrict__ kf,
                 const float* __restrict__ v,
                 bf16* __restrict__ a0out, bf16* __restrict__ a1out)
{
    __shared__ float qs[8][64];

    const int wlocal = threadIdx.x >> 5;
    const int gwarp = (blockIdx.x * blockDim.x + threadIdx.x) >> 5;
    const int lane = threadIdx.x & 31;
    if (gwarp >= BH * QLEN) return;

    const int m = gwarp % QLEN;
    const int h = (gwarp / QLEN) % NHEAD;
    const int b = gwarp / (QLEN * NHEAD);
    const size_t bh = (size_t)b * NHEAD + h;

    // ---- phase 1: lane-private top-TK of this lane's 128 strided scores ----
    float tb[TK]; int ib[TK];
#pragma unroll
    for (int j = 0; j < TK; j++) { tb[j] = -INFINITY; ib[j] = 0; }

    const uint4* srow = reinterpret_cast<const uint4*>(scb + (size_t)gwarp * KVLEN);
#pragma unroll 1
    for (int c = 0; c < 16; c++) {
        const uint4 pk = srow[c * 32 + lane];
        const int base = (c * 32 + lane) * 8;
        const uint32_t ws[4] = {pk.x, pk.y, pk.z, pk.w};
#pragma unroll
        for (int e = 0; e < 4; e++) {
            const bf162 pr = *reinterpret_cast<const bf162*>(&ws[e]);
            const float v0 = __low2float(pr);
            const float v1 = __high2float(pr);
#pragma unroll
            for (int half = 0; half < 2; half++) {
                float cv = half ? v1 : v0;
                int ci = base + e * 2 + half;
                if (cv > tb[TK - 1]) {
#pragma unroll
                    for (int j = 0; j < TK; j++) {
                        if (cv > tb[j]) {
                            const float tv = tb[j]; const int tx2 = ib[j];
                            tb[j] = cv; ib[j] = ci; cv = tv; ci = tx2;
                        }
                    }
                }
            }
        }
    }

    const float tau = warp_min(tb[1]) - 0.02f;

    // ---- phase 2: exact sequential-fp32 rescore of candidates >= tau ----
    {
        const float* qrow = qf + (bh * QLEN + m) * 64;
        if (lane < 16)
            *reinterpret_cast<float4*>(&qs[wlocal][lane * 4]) =
                *reinterpret_cast<const float4*>(qrow + lane * 4);
        __syncwarp();
    }
    const float* kbase = kf + bh * KVLEN * 64;
    float es[TK];
#pragma unroll
    for (int j = 0; j < TK; j++) {
        es[j] = -INFINITY;
        if (tb[j] >= tau) {
            const float* kr = kbase + (size_t)ib[j] * 64;
            float acc = 0.f;
#pragma unroll
            for (int t = 0; t < 16; t++) {
                const float4 k4 = *reinterpret_cast<const float4*>(kr + t * 4);
                const float4 q4 = *reinterpret_cast<const float4*>(&qs[wlocal][t * 4]);
                acc = fmaf(q4.x, k4.x, acc);
                acc = fmaf(q4.y, k4.y, acc);
                acc = fmaf(q4.z, k4.z, acc);
                acc = fmaf(q4.w, k4.w, acc);
            }
            es[j] = acc * 0.125f;
        }
    }

    // ---- phase 3: merge per-lane rounds into warp-wide exact top-32 ----
    float ls = es[0];
    int   li = ib[0];
#pragma unroll
    for (int r = 1; r < TK; r++) {
        const float cnd = es[r];
        const int cidx = ib[r];
        const float curmin = warp_min(ls);
        unsigned mask = __ballot_sync(FULLMASK, cnd > curmin);
        while (mask) {
            const int src = __ffs(mask) - 1;
            mask &= mask - 1;
            const float cand = __shfl_sync(FULLMASK, cnd, src);
            float mv; int ml;
            warp_argmin(ls, lane, mv, ml);
            if (cand > mv) {
                const int candidx = __shfl_sync(FULLMASK, cidx, src);
                if (lane == ml) { ls = cand; li = candidx; }
            }
        }
    }

    // ---- softmax on exact scores + V gather ----
    const float mx = warp_max(ls);
    float w = expf(ls - mx);
    const float Z = warp_sum(w);
    w /= Z;

    const float* vb = v + bh * KVLEN * 64;
    float a0 = 0.f, a1 = 0.f;
#pragma unroll
    for (int e = 0; e < TOPK; e++) {
        const float we = __shfl_sync(FULLMASK, w, e);
        const int   ie = __shfl_sync(FULLMASK, li, e);
        const float* vr = vb + (size_t)ie * 64;
        a0 = fmaf(we, vr[lane], a0);
        a1 = fmaf(we, vr[lane + 32], a1);
    }

    const size_t dst = ((size_t)b * QLEN + m) * HID + h * 64;
    bf16 pl0 = __float2bfloat16(a0);
    bf16 pl1 = __float2bfloat16(a1);
    a0out[dst + lane]      = pl0;
    a0out[dst + lane + 32] = pl1;
    a1out[dst + lane]      = __float2bfloat16(a0 - __bfloat162float(pl0));
    a1out[dst + lane + 32] = __float2bfloat16(a1 - __bfloat162float(pl1));
}

// ---------------------------------------------------------------------------
// Host launcher (R13 layout; fused Q+K projection launch; Wo split moved
// behind the projections)
// ---------------------------------------------------------------------------
extern "C" void kernel_launch(void* const* d_in, const int* in_sizes, int n_in,
                              void* d_out, int out_size)
{
    const float* query = (const float*)d_in[0];
    const float* key   = (const float*)d_in[1];
    const float* value = (const float*)d_in[2];
    const float* Wq = (const float*)d_in[3];
    const float* bq = (const float*)d_in[4];
    const float* Wk = (const float*)d_in[5];
    const float* bk = (const float*)d_in[6];
    const float* Wv = (const float*)d_in[7];
    const float* bv = (const float*)d_in[8];
    const float* Wo = (const float*)d_in[9];
    const float* bo = (const float*)d_in[10];
    float* out = (float*)d_out;

    float *q, *k, *v;
    bf16 *qb, *kb, *scb, *vs0, *vs1, *wv0, *wv1, *wo0, *wo1, *at0, *at1;
    cudaGetSymbolAddress((void**)&q, g_q);
    cudaGetSymbolAddress((void**)&k, g_k);
    cudaGetSymbolAddress((void**)&v, g_v);
    cudaGetSymbolAddress((void**)&qb, g_qb);
    cudaGetSymbolAddress((void**)&kb, g_kb);
    cudaGetSymbolAddress((void**)&scb, g_scb);
    cudaGetSymbolAddress((void**)&vs0, g_vs0);
    cudaGetSymbolAddress((void**)&vs1, g_vs1);
    cudaGetSymbolAddress((void**)&wv0, g_wv0);
    cudaGetSymbolAddress((void**)&wv1, g_wv1);
    cudaGetSymbolAddress((void**)&wo0, g_wo0);
    cudaGetSymbolAddress((void**)&wo1, g_wo1);
    cudaGetSymbolAddress((void**)&at0, g_at0);
    cudaGetSymbolAddress((void**)&at1, g_at1);

    const int SSM = 2 * 20480;
    const int PSM = 3 * 20480;
    cudaFuncSetAttribute(score_bf16, cudaFuncAttributeMaxDynamicSharedMemorySize, SSM);
    cudaFuncSetAttribute(proj_mma<1>, cudaFuncAttributeMaxDynamicSharedMemorySize, PSM);
    cudaFuncSetAttribute(proj_mma<2>, cudaFuncAttributeMaxDynamicSharedMemorySize, PSM);

    static cudaStream_t s_v = nullptr;
    static cudaEvent_t ev_fork = nullptr, ev_join = nullptr;
    if (!s_v) {
        cudaStreamCreateWithFlags(&s_v, cudaStreamNonBlocking);
        cudaEventCreateWithFlags(&ev_fork, cudaEventDisableTiming);
        cudaEventCreateWithFlags(&ev_join, cudaEventDisableTiming);
    }

    const dim3 blk(256);

    // fork side stream
    cudaEventRecord(ev_fork, 0);
    cudaStreamWaitEvent(s_v, ev_fork, 0);

    // side stream: split value + Wv, then V projection (HMMA 2-split)
    split2_k<<<(MKV * HID / 4 + 255) / 256, 256, 0, s_v>>>(value, vs0, vs1, MKV * HID / 4);
    split2_k<<<(HID * HID / 4 + 255) / 256, 256, 0, s_v>>>(Wv, wv0, wv1, HID * HID / 4);
    proj_mma<1><<<dim3(8, MKV / 128), blk, PSM, s_v>>>(vs0, vs1, wv0, wv1, bv, v, KVLEN);
    cudaEventRecord(ev_join, s_v);

    // main stream: fused Q+K projection (one grid, better wave fill)
    gemm_qk_fused<<<dim3(HID / 128, MQ / 128 + MKV / 128), blk>>>(
        query, Wq, bq, key, Wk, bk, q, qb, k, kb);

    // Wo split (off the projection critical path head)
    split2_k<<<(HID * HID / 4 + 255) / 256, 256>>>(Wo, wo0, wo1, HID * HID / 4);

    score_bf16<<<dim3(KVLEN / 128, QLEN / 128, BH), 512, SSM>>>(qb, kb, scb);

    // join: topk needs v
    cudaStreamWaitEvent(0, ev_join, 0);

    // Top-k (frozen R13 body)
    topk_attend<<<(BH * QLEN) / 8, blk>>>(scb, q, k, v, at0, at1);

    // Output projection (HMMA 2-split) -> d_out
    proj_mma<2><<<dim3(8, MQ / 128), blk, PSM>>>(at0, at1, wo0, wo1, bo, out, 0);
}